// round 3
// baseline (speedup 1.0000x reference)
#include <cuda_runtime.h>
#include <math.h>

#define TT   4096
#define DIM  1024
#define HID  4096
#define NE   8
#define TOPK 2
#define NP   (TT * TOPK)   // 8192 (token, k) pairs

// ---------------- device scratch (static allocation, allowed) --------------
__device__ float g_h[(size_t)NP * HID];   // 128 MB: relu(x@w1+b1) per pair
__device__ int   g_cnt[NE];
__device__ int   g_off[NE];
__device__ int   g_cur[NE];
__device__ int   g_tok[NP];               // token id per pair (expert-segmented)
__device__ float g_prob[NP];              // combine weight per pair
__device__ int   g_top_idx[TT * TOPK];
__device__ float g_top_p[TT * TOPK];

// ---------------- small kernels -------------------------------------------
__global__ void zero_meta_kernel() {
    int i = threadIdx.x;
    if (i < NE) { g_cnt[i] = 0; g_cur[i] = 0; }
}

__global__ void zero_out_kernel(float4* out, int n4) {
    int i = blockIdx.x * blockDim.x + threadIdx.x;
    int stride = gridDim.x * blockDim.x;
    float4 z = make_float4(0.f, 0.f, 0.f, 0.f);
    for (; i < n4; i += stride) out[i] = z;
}

// one warp per token: logits -> softmax -> top2 -> counts
__global__ void gate_kernel(const float* __restrict__ x,
                            const float* __restrict__ gw,
                            const float* __restrict__ gb) {
    int warp = (blockIdx.x * blockDim.x + threadIdx.x) >> 5;
    int lane = threadIdx.x & 31;
    if (warp >= TT) return;
    const float* xr = x + (size_t)warp * DIM;

    float acc[NE];
#pragma unroll
    for (int e = 0; e < NE; e++) acc[e] = 0.f;

    for (int d = lane; d < DIM; d += 32) {
        float xv = xr[d];
        const float* g = gw + d * NE;
#pragma unroll
        for (int e = 0; e < NE; e++) acc[e] += xv * g[e];
    }
#pragma unroll
    for (int e = 0; e < NE; e++) {
#pragma unroll
        for (int s = 16; s > 0; s >>= 1)
            acc[e] += __shfl_xor_sync(0xffffffffu, acc[e], s);
    }
    if (lane == 0) {
        float l[NE], p[NE];
        float m = -1e30f;
#pragma unroll
        for (int e = 0; e < NE; e++) { l[e] = acc[e] + gb[e]; m = fmaxf(m, l[e]); }
        float s = 0.f;
#pragma unroll
        for (int e = 0; e < NE; e++) { p[e] = __expf(l[e] - m); s += p[e]; }
        float inv = 1.f / s;
#pragma unroll
        for (int e = 0; e < NE; e++) p[e] *= inv;

        int i1 = 0; float p1 = p[0];
#pragma unroll
        for (int e = 1; e < NE; e++) if (p[e] > p1) { p1 = p[e]; i1 = e; }
        int i2 = -1; float p2 = -1.f;
#pragma unroll
        for (int e = 0; e < NE; e++)
            if (e != i1 && p[e] > p2) { p2 = p[e]; i2 = e; }

        g_top_idx[warp * 2 + 0] = i1; g_top_p[warp * 2 + 0] = p1;
        g_top_idx[warp * 2 + 1] = i2; g_top_p[warp * 2 + 1] = p2;
        atomicAdd(&g_cnt[i1], 1);
        atomicAdd(&g_cnt[i2], 1);
    }
}

__global__ void offsets_kernel() {
    if (threadIdx.x == 0) {
        int s = 0;
        for (int e = 0; e < NE; e++) { g_off[e] = s; s += g_cnt[e]; }
    }
}

__global__ void scatter_kernel() {
    int t = blockIdx.x * blockDim.x + threadIdx.x;
    if (t >= TT) return;
#pragma unroll
    for (int k = 0; k < TOPK; k++) {
        int e = g_top_idx[t * 2 + k];
        int slot = g_off[e] + atomicAdd(&g_cur[e], 1);
        g_tok[slot]  = t;
        g_prob[slot] = g_top_p[t * 2 + k];
    }
}

// ---------------- TF32 tensor-core GEMM ------------------------------------
// Block 128x128, K-tile 32. 256 threads = 8 warps in 2(m) x 4(n) grid.
// Warp tile 64x32 = 4x4 m16n8k8 mma tiles. fp32 accumulate.
// A staged [m][k] stride 36 (conflict-free frag loads: bank=4*(lane/4)+lane%4).
// B staged [k][n] stride 136 (bank=8*(lane%4)+lane/4).

#define BM 128
#define BN 128
#define BK 32
#define ASTRIDE 36
#define BSTRIDE 136

__device__ __forceinline__ unsigned f2tf(float f) {
    unsigned r;
    asm("cvt.rna.tf32.f32 %0, %1;" : "=r"(r) : "f"(f));
    return r;
}

#define MMA_TF32(d, A_, B_)                                                    \
    asm volatile(                                                              \
        "mma.sync.aligned.m16n8k8.row.col.f32.tf32.tf32.f32 "                  \
        "{%0,%1,%2,%3},{%4,%5,%6,%7},{%8,%9},{%0,%1,%2,%3};"                   \
        : "+f"(d[0]), "+f"(d[1]), "+f"(d[2]), "+f"(d[3])                       \
        : "r"(A_[0]), "r"(A_[1]), "r"(A_[2]), "r"(A_[3]),                      \
          "r"(B_[0]), "r"(B_[1]))

// GEMM1: H[pair, h] = relu( x[tok[pair], :] @ w1[e] + b1[e] ),  K=DIM, N=HID
__global__ __launch_bounds__(256) void gemm1_kernel(
        const float* __restrict__ x,
        const float* __restrict__ w1,
        const float* __restrict__ b1) {
    int e   = blockIdx.z;
    int cnt = g_cnt[e];
    int m0  = blockIdx.y * BM;
    if (m0 >= cnt) return;
    int n0  = blockIdx.x * BN;
    int off = g_off[e];
    const float* B = w1 + (size_t)e * DIM * HID;   // [DIM][HID]

    __shared__ unsigned As[BM * ASTRIDE];
    __shared__ unsigned Bs[BK * BSTRIDE];

    int tid  = threadIdx.x;
    int lane = tid & 31;
    int wid  = tid >> 5;
    int mw   = (wid >> 2) * 64;       // warp m-offset in tile
    int nw   = (wid & 3) * 32;        // warp n-offset in tile
    int lm   = lane >> 2;             // 0..7
    int lk   = lane & 3;              // 0..3

    // A staging: thread -> row (tid>>3)+32p, colgroup (tid&7)*4
    int ar = tid >> 3, ac = (tid & 7) * 4;
    const float* aptr[4];
#pragma unroll
    for (int p = 0; p < 4; p++) {
        int m = m0 + ar + 32 * p;
        if (m >= cnt) m = cnt - 1;
        aptr[p] = x + (size_t)g_tok[off + m] * DIM + ac;
    }
    // B staging: thread -> k-row (tid>>5)+8p, colgroup (tid&31)*4
    int bk = tid >> 5, bc = (tid & 31) * 4;
    const float* bptr = B + (size_t)bk * HID + n0 + bc;

    float acc[4][4][4];
#pragma unroll
    for (int i = 0; i < 4; i++)
#pragma unroll
        for (int j = 0; j < 4; j++)
#pragma unroll
            for (int r = 0; r < 4; r++) acc[i][j][r] = 0.f;

    float4 pa[4], pb[4];
#pragma unroll
    for (int p = 0; p < 4; p++) {
        pa[p] = *(const float4*)(aptr[p]);
        pb[p] = *(const float4*)(bptr + (size_t)(8 * p) * HID);
    }

    for (int kt = 0; kt < DIM; kt += BK) {
#pragma unroll
        for (int p = 0; p < 4; p++) {
            unsigned* as = &As[(ar + 32 * p) * ASTRIDE + ac];
            as[0] = f2tf(pa[p].x); as[1] = f2tf(pa[p].y);
            as[2] = f2tf(pa[p].z); as[3] = f2tf(pa[p].w);
            unsigned* bs = &Bs[(bk + 8 * p) * BSTRIDE + bc];
            bs[0] = f2tf(pb[p].x); bs[1] = f2tf(pb[p].y);
            bs[2] = f2tf(pb[p].z); bs[3] = f2tf(pb[p].w);
        }
        __syncthreads();
        int ktn = kt + BK;
        if (ktn < DIM) {
#pragma unroll
            for (int p = 0; p < 4; p++) {
                pa[p] = *(const float4*)(aptr[p] + ktn);
                pb[p] = *(const float4*)(bptr + (size_t)(ktn + 8 * p) * HID);
            }
        }
#pragma unroll
        for (int ks = 0; ks < BK; ks += 8) {
            unsigned af[4][4], bf[4][2];
#pragma unroll
            for (int mt = 0; mt < 4; mt++) {
                int mb = mw + mt * 16 + lm;
                af[mt][0] = As[(mb    ) * ASTRIDE + ks + lk];
                af[mt][1] = As[(mb + 8) * ASTRIDE + ks + lk];
                af[mt][2] = As[(mb    ) * ASTRIDE + ks + lk + 4];
                af[mt][3] = As[(mb + 8) * ASTRIDE + ks + lk + 4];
            }
#pragma unroll
            for (int nt = 0; nt < 4; nt++) {
                int nb = nw + nt * 8 + lm;
                bf[nt][0] = Bs[(ks + lk    ) * BSTRIDE + nb];
                bf[nt][1] = Bs[(ks + lk + 4) * BSTRIDE + nb];
            }
#pragma unroll
            for (int mt = 0; mt < 4; mt++)
#pragma unroll
                for (int nt = 0; nt < 4; nt++)
                    MMA_TF32(acc[mt][nt], af[mt], bf[nt]);
        }
        __syncthreads();
    }

    // epilogue: relu(acc + b1) -> g_h
#pragma unroll
    for (int nt = 0; nt < 4; nt++) {
        int gn = n0 + nw + nt * 8 + 2 * lk;
        float bv0 = b1[e * HID + gn];
        float bv1 = b1[e * HID + gn + 1];
#pragma unroll
        for (int mt = 0; mt < 4; mt++) {
            int m_lo = mw + mt * 16 + lm;
            if (m0 + m_lo < cnt) {
                float2 v;
                v.x = fmaxf(acc[mt][nt][0] + bv0, 0.f);
                v.y = fmaxf(acc[mt][nt][1] + bv1, 0.f);
                *(float2*)(g_h + (size_t)(off + m0 + m_lo) * HID + gn) = v;
            }
            if (m0 + m_lo + 8 < cnt) {
                float2 v;
                v.x = fmaxf(acc[mt][nt][2] + bv0, 0.f);
                v.y = fmaxf(acc[mt][nt][3] + bv1, 0.f);
                *(float2*)(g_h + (size_t)(off + m0 + m_lo + 8) * HID + gn) = v;
            }
        }
    }
}

// GEMM2: out[tok, d] += p * ( H[pair, :] @ w2[e] + b2[e] ),  K=HID, N=DIM
__global__ __launch_bounds__(256) void gemm2_kernel(
        const float* __restrict__ w2,
        const float* __restrict__ b2,
        float* __restrict__ out) {
    int e   = blockIdx.z;
    int cnt = g_cnt[e];
    int m0  = blockIdx.y * BM;
    if (m0 >= cnt) return;
    int n0  = blockIdx.x * BN;
    int off = g_off[e];
    const float* B = w2 + (size_t)e * HID * DIM;   // [HID][DIM]

    __shared__ unsigned As[BM * ASTRIDE];
    __shared__ unsigned Bs[BK * BSTRIDE];

    int tid  = threadIdx.x;
    int lane = tid & 31;
    int wid  = tid >> 5;
    int mw   = (wid >> 2) * 64;
    int nw   = (wid & 3) * 32;
    int lm   = lane >> 2;
    int lk   = lane & 3;

    int ar = tid >> 3, ac = (tid & 7) * 4;
    const float* aptr[4];
#pragma unroll
    for (int p = 0; p < 4; p++) {
        int m = m0 + ar + 32 * p;
        if (m >= cnt) m = cnt - 1;
        aptr[p] = g_h + (size_t)(off + m) * HID + ac;
    }
    int bk = tid >> 5, bc = (tid & 31) * 4;
    const float* bptr = B + (size_t)bk * DIM + n0 + bc;

    float acc[4][4][4];
#pragma unroll
    for (int i = 0; i < 4; i++)
#pragma unroll
        for (int j = 0; j < 4; j++)
#pragma unroll
            for (int r = 0; r < 4; r++) acc[i][j][r] = 0.f;

    float4 pa[4], pb[4];
#pragma unroll
    for (int p = 0; p < 4; p++) {
        pa[p] = *(const float4*)(aptr[p]);
        pb[p] = *(const float4*)(bptr + (size_t)(8 * p) * DIM);
    }

    for (int kt = 0; kt < HID; kt += BK) {
#pragma unroll
        for (int p = 0; p < 4; p++) {
            unsigned* as = &As[(ar + 32 * p) * ASTRIDE + ac];
            as[0] = f2tf(pa[p].x); as[1] = f2tf(pa[p].y);
            as[2] = f2tf(pa[p].z); as[3] = f2tf(pa[p].w);
            unsigned* bs = &Bs[(bk + 8 * p) * BSTRIDE + bc];
            bs[0] = f2tf(pb[p].x); bs[1] = f2tf(pb[p].y);
            bs[2] = f2tf(pb[p].z); bs[3] = f2tf(pb[p].w);
        }
        __syncthreads();
        int ktn = kt + BK;
        if (ktn < HID) {
#pragma unroll
            for (int p = 0; p < 4; p++) {
                pa[p] = *(const float4*)(aptr[p] + ktn);
                pb[p] = *(const float4*)(bptr + (size_t)(ktn + 8 * p) * DIM);
            }
        }
#pragma unroll
        for (int ks = 0; ks < BK; ks += 8) {
            unsigned af[4][4], bf[4][2];
#pragma unroll
            for (int mt = 0; mt < 4; mt++) {
                int mb = mw + mt * 16 + lm;
                af[mt][0] = As[(mb    ) * ASTRIDE + ks + lk];
                af[mt][1] = As[(mb + 8) * ASTRIDE + ks + lk];
                af[mt][2] = As[(mb    ) * ASTRIDE + ks + lk + 4];
                af[mt][3] = As[(mb + 8) * ASTRIDE + ks + lk + 4];
            }
#pragma unroll
            for (int nt = 0; nt < 4; nt++) {
                int nb = nw + nt * 8 + lm;
                bf[nt][0] = Bs[(ks + lk    ) * BSTRIDE + nb];
                bf[nt][1] = Bs[(ks + lk + 4) * BSTRIDE + nb];
            }
#pragma unroll
            for (int mt = 0; mt < 4; mt++)
#pragma unroll
                for (int nt = 0; nt < 4; nt++)
                    MMA_TF32(acc[mt][nt], af[mt], bf[nt]);
        }
        __syncthreads();
    }

    // epilogue: atomicAdd p*(acc + b2) into out (2 deterministic addends/elem)
#pragma unroll
    for (int nt = 0; nt < 4; nt++) {
        int gn = n0 + nw + nt * 8 + 2 * lk;
        float bv0 = b2[e * DIM + gn];
        float bv1 = b2[e * DIM + gn + 1];
#pragma unroll
        for (int mt = 0; mt < 4; mt++) {
#pragma unroll
            for (int half = 0; half < 2; half++) {
                int m_lo = mw + mt * 16 + lm + 8 * half;
                if (m0 + m_lo < cnt) {
                    int pair = off + m0 + m_lo;
                    int tok  = g_tok[pair];
                    float p  = g_prob[pair];
                    float* orow = out + (size_t)tok * DIM + gn;
                    atomicAdd(&orow[0], p * (acc[mt][nt][2 * half]     + bv0));
                    atomicAdd(&orow[1], p * (acc[mt][nt][2 * half + 1] + bv1));
                }
            }
        }
    }
}

// ---------------- launcher --------------------------------------------------
extern "C" void kernel_launch(void* const* d_in, const int* in_sizes, int n_in,
                              void* d_out, int out_size) {
    const float* x  = (const float*)d_in[0];
    const float* gw = (const float*)d_in[1];
    const float* gb = (const float*)d_in[2];
    const float* w1 = (const float*)d_in[3];
    const float* b1 = (const float*)d_in[4];
    const float* w2 = (const float*)d_in[5];
    const float* b2 = (const float*)d_in[6];
    float* out = (float*)d_out;

    zero_meta_kernel<<<1, 32>>>();
    zero_out_kernel<<<1024, 256>>>((float4*)out, TT * DIM / 4);
    gate_kernel<<<TT / 4, 128>>>(x, gw, gb);
    offsets_kernel<<<1, 1>>>();
    scatter_kernel<<<(TT + 255) / 256, 256>>>();
    gemm1_kernel<<<dim3(HID / BN, TT / BM, NE), 256>>>(x, w1, b1);
    gemm2_kernel<<<dim3(DIM / BN, TT / BM, NE), 256>>>(w2, b2, out);
}